// round 6
// baseline (speedup 1.0000x reference)
#include <cuda_runtime.h>
#include <math.h>

#define IMG 256
#define MAX_R 64
#define N_AG 2047
#define N_OB 2048
#define N_ENT 4095
#define FOVH 0.7853981633974483f   /* pi/4 = FOV/2 */
#define PT 1024

/* fixed-slot records: {pxi<<16 | pr*pr, depth_bits}; invalid => pxi = -30000 */
__device__ uint2 g_rec[4096];

__global__ void transform_kernel(const float* __restrict__ agent,
                                 const float* __restrict__ goal,
                                 const float* __restrict__ others,
                                 const float* __restrict__ obs) {
    int e = blockIdx.x * blockDim.x + threadIdx.x;
    if (e >= N_ENT) return;

    float ax = agent[0], ay = agent[1];
    float vx = goal[0] - ax, vy = goal[1] - ay;
    float inv = 1.0f / (sqrtf(vx * vx + vy * vy) + 1e-8f);
    vx *= inv; vy *= inv;
    float c = vy, s = vx;

    float ex, ey, r, h;
    if (e < N_AG) {
        ex = others[2 * e];
        ey = others[2 * e + 1];
        r  = 0.05f;
        h  = 0.2f;
    } else {
        int o = e - N_AG;
        ex = obs[3 * o];
        ey = obs[3 * o + 1];
        r  = obs[3 * o + 2];
        h  = 0.5f;
    }

    float rx = ex - ax, ry = ey - ay;
    float camx =  c * rx + s * ry;
    float camy = -s * rx + c * ry;
    float dist = sqrtf(camx * camx + camy * camy);
    float angle = atan2f(camx, camy);

    uint2 rec;
    if ((camy >= 0.0f) && (dist <= 3.0f) && (fabsf(angle) <= FOVH)) {
        float pixel_x = angle / FOVH * 0.5f;
        int pxi = (int)floorf((pixel_x + 0.5f) * (float)IMG);
        int pr  = (int)floorf(r / (dist + 1e-8f) * (float)IMG * 0.5f);
        pr = min(max(pr, 1), MAX_R);
        float depth = fminf(dist / 3.0f, 1.0f) * (1.0f - h * 0.3f);
        depth = fmaxf(depth, 0.0f);
        rec.x = ((unsigned)pxi << 16) | (unsigned)(pr * pr);
        rec.y = __float_as_uint(depth);
    } else {
        rec.x = ((unsigned)(-30000) << 16);   /* never overlaps any column */
        rec.y = __float_as_uint(1.0f);
    }
    g_rec[e] = rec;
}

__global__ __launch_bounds__(PT, 2)
void paint_kernel(float* __restrict__ out) {
    __shared__ uint2 s_rec[N_ENT];     /* {rem = pr2-dx2, depth_bits} */
    __shared__ int   s_wcnt[32];
    __shared__ int   s_wbase[33];
    __shared__ float s_min[PT];

    int tid  = threadIdx.x;
    int col  = blockIdx.x;
    int warp = tid >> 5;
    unsigned lane = tid & 31;

    /* Phase A0: batched loads (4 independent LDG.64 in flight) */
    uint2 r[4];
    #pragma unroll
    for (int k = 0; k < 4; k++) {
        int e = tid + k * PT;
        r[k] = (e < N_ENT) ? __ldg(&g_rec[e])
                           : make_uint2(((unsigned)(-30000)) << 16, 0u);
    }

    /* Phase A1: hit test + per-warp counts (registers only, no atomics) */
    int rem[4]; unsigned msk[4]; int cnt = 0;
    #pragma unroll
    for (int k = 0; k < 4; k++) {
        int pxi = (int)r[k].x >> 16;          /* arithmetic shift: sign ok */
        int pr2 = (int)(r[k].x & 0xffffu);
        int dx  = col - pxi;
        rem[k]  = pr2 - dx * dx;              /* |dx| <= ~30256 -> no ovf */
        msk[k]  = __ballot_sync(0xffffffffu, rem[k] >= 0);
        cnt    += __popc(msk[k]);
    }
    if (lane == 0) s_wcnt[warp] = cnt;
    __syncthreads();

    /* exclusive scan of 32 warp counts (warp 0) */
    if (warp == 0) {
        int v = s_wcnt[lane];
        int incl = v;
        #pragma unroll
        for (int off = 1; off < 32; off <<= 1) {
            int t = __shfl_up_sync(0xffffffffu, incl, off);
            if ((int)lane >= off) incl += t;
        }
        s_wbase[lane] = incl - v;
        if (lane == 31) s_wbase[32] = incl;
    }
    __syncthreads();

    /* Phase A2: write hits into exclusive warp segments */
    int base = s_wbase[warp];
    #pragma unroll
    for (int k = 0; k < 4; k++) {
        if (rem[k] >= 0) {
            int pos = base + __popc(msk[k] & ((1u << lane) - 1));
            s_rec[pos] = make_uint2((unsigned)rem[k], r[k].y);
        }
        base += __popc(msk[k]);
    }
    __syncthreads();
    int n = s_wbase[32];

    /* Phase B: 4 threads per row scan interleaved quarters.
       Rows with dy^2 > 4096 can never be hit (pr <= 64) -> skip. */
    int row = tid & 255;
    int q   = tid >> 8;
    int dy  = row - IMG / 2;
    int d2  = dy * dy;
    float mv = 1.0f;
    if (d2 <= MAX_R * MAX_R) {
        #pragma unroll 4
        for (int e = q; e < n; e += 4) {
            uint2 rr = s_rec[e];
            if (d2 <= (int)rr.x) mv = fminf(mv, __uint_as_float(rr.y));
        }
    }
    s_min[tid] = mv;
    __syncthreads();

    if (tid < 256) {
        float a = fminf(s_min[tid],        s_min[tid + 256]);
        float b = fminf(s_min[tid + 512],  s_min[tid + 768]);
        out[tid * IMG + col] = fminf(a, b);
    }
}

extern "C" void kernel_launch(void* const* d_in, const int* in_sizes, int n_in,
                              void* d_out, int out_size) {
    const float* agent  = (const float*)d_in[0];
    const float* goal   = (const float*)d_in[1];
    const float* others = (const float*)d_in[2];
    const float* obs    = (const float*)d_in[3];
    float* out          = (float*)d_out;

    transform_kernel<<<128, 32>>>(agent, goal, others, obs);
    paint_kernel<<<IMG, PT>>>(out);
}